// round 5
// baseline (speedup 1.0000x reference)
#include <cuda_runtime.h>

// ---------------------------------------------------------------------------
// CarryII R5: owner-writes CSR, restructured to be loop-free and shallow.
//   zero : cnt=0, s0=-1
//   count: one fused kernel over all 13M edges -> cnt[dst]++
//   scan : 3-pass exclusive scan -> off (cursor kept in cnt)
//   fill : pos=cursor[row]++; if pos==off[row] -> s0[row]=s, node[pos]=sentinel
//                             else               node[pos]={s,row}
//   A    : row-parallel (8 lanes/row): s0 -> feat -> single __stcs   (no loop)
//   B    : slot-parallel: node[j] -> (26% of slots) feat -> red.v4
// B runs after A (stream order), so REDs accumulate onto A's stores.
// ---------------------------------------------------------------------------

static constexpr int FEAT_D = 32;
static constexpr int N3C = 1500000;
static constexpr int N4C = 2000000;
static constexpr long long TOT = 2LL * N3C + 5LL * N4C;   // 13,000,000
static constexpr int SCAN_CHUNK = 4096;
static constexpr int NB = (int)((TOT + SCAN_CHUNK - 1) / SCAN_CHUNK);  // 3174

__device__ int  g_cnt[TOT];       // counts -> cursors
__device__ int  g_off[TOT + 1];
__device__ int  g_s0[TOT];        // first contributing src per row, -1 if none
__device__ int2 g_node[TOT];      // {src,row} for non-first slots, {-1,-1} first
__device__ int  g_bs[NB];
__device__ int  g_bs_ex[NB];

struct EdgePtrs {                 // 7 relations, concatenated edge space
    const int* s[7];
    const int* d[7];
    int ebase[8];                 // edge/row block bases (same layout), +end
};

__device__ __forceinline__ int find_rel(const EdgePtrs& ep, int ge) {
    int r = 0;
    #pragma unroll
    for (int k = 1; k < 7; k++) r += (ge >= ep.ebase[k]);
    return r;
}

__global__ void init_kernel() {
    long long i = blockIdx.x * (long long)blockDim.x + threadIdx.x;
    long long q = TOT / 4;
    if (i < q)          ((int4*)g_cnt)[i]     = make_int4(0, 0, 0, 0);
    else if (i < 2 * q) ((int4*)g_s0)[i - q]  = make_int4(-1, -1, -1, -1);
}

__global__ void count_kernel(EdgePtrs ep) {
    int ge = blockIdx.x * blockDim.x + threadIdx.x;
    if (ge >= (int)TOT) return;
    int r = find_rel(ep, ge);
    int d = __ldcs(ep.d[r] + (ge - ep.ebase[r]));
    atomicAdd(g_cnt + ep.ebase[r] + d, 1);
}

__global__ void scan_block_sum_kernel() {
    __shared__ int sh[256];
    long long base = (long long)blockIdx.x * SCAN_CHUNK;
    int t = threadIdx.x;
    int sum = 0;
    #pragma unroll
    for (int k = 0; k < 16; k++) {
        long long i = base + t + k * 256;
        if (i < TOT) sum += g_cnt[i];
    }
    sh[t] = sum; __syncthreads();
    for (int s = 128; s > 0; s >>= 1) {
        if (t < s) sh[t] += sh[t + s];
        __syncthreads();
    }
    if (t == 0) g_bs[blockIdx.x] = sh[0];
}

__global__ void scan_bs_kernel() {
    __shared__ int sh[1024];
    int t = threadIdx.x;
    int vals[4]; int sum = 0;
    #pragma unroll
    for (int k = 0; k < 4; k++) {
        int i = t * 4 + k;
        vals[k] = (i < NB) ? g_bs[i] : 0;
        sum += vals[k];
    }
    sh[t] = sum; __syncthreads();
    for (int ofs = 1; ofs < 1024; ofs <<= 1) {
        int v = (t >= ofs) ? sh[t - ofs] : 0;
        __syncthreads();
        sh[t] += v;
        __syncthreads();
    }
    int run = sh[t] - sum;
    #pragma unroll
    for (int k = 0; k < 4; k++) {
        int i = t * 4 + k;
        if (i < NB) g_bs_ex[i] = run;
        run += vals[k];
    }
}

__global__ void scan_fill_off_kernel() {
    __shared__ int sh[256];
    int t = threadIdx.x;
    long long my = (long long)blockIdx.x * SCAN_CHUNK + (long long)t * 16;
    int vals[16]; int sum = 0;
    #pragma unroll
    for (int k = 0; k < 16; k++) {
        long long i = my + k;
        vals[k] = (i < TOT) ? g_cnt[i] : 0;
        sum += vals[k];
    }
    sh[t] = sum; __syncthreads();
    for (int ofs = 1; ofs < 256; ofs <<= 1) {
        int v = (t >= ofs) ? sh[t - ofs] : 0;
        __syncthreads();
        sh[t] += v;
        __syncthreads();
    }
    int run = (sh[t] - sum) + g_bs_ex[blockIdx.x];
    #pragma unroll
    for (int k = 0; k < 16; k++) {
        long long i = my + k;
        if (i < TOT) { g_off[i] = run; g_cnt[i] = run; run += vals[k]; }
    }
    if (my + 16 == TOT) g_off[TOT] = run;
}

__global__ void fill_kernel(EdgePtrs ep) {
    int ge = blockIdx.x * blockDim.x + threadIdx.x;
    if (ge >= (int)TOT) return;
    int r = find_rel(ep, ge);
    int le = ge - ep.ebase[r];
    int s = __ldcs(ep.s[r] + le);
    int d = __ldcs(ep.d[r] + le);
    int grow = ep.ebase[r] + d;
    int pos = atomicAdd(g_cnt + grow, 1);
    if (pos == __ldg(g_off + grow)) {
        g_s0[grow] = s;                       // first slot -> direct store path
        g_node[pos] = make_int2(-1, -1);      // sentinel for kernel B
    } else {
        g_node[pos] = make_int2(s, grow);
    }
}

// Kernel A: one store per output row; chain = s0 -> feat -> st. No loops.
__global__ void store_rows_kernel(const float4* __restrict__ u2,
                                  const float4* __restrict__ u3,
                                  float4* __restrict__ out,
                                  int u3_row_base) {
    long long gid = blockIdx.x * (long long)blockDim.x + threadIdx.x;
    int row = (int)(gid >> 3);
    if (row >= (int)TOT) return;
    int sub = (int)(gid & 7);

    int s0 = __ldg(g_s0 + row);               // coalesced, broadcast per group
    float4 v = make_float4(0.f, 0.f, 0.f, 0.f);
    if (s0 >= 0) {
        const float4* feat = (row < u3_row_base) ? u2 : u3;
        v = __ldg(feat + (long long)s0 * 8 + sub);
    }
    __stcs(out + (long long)row * 8 + sub, v);
}

__device__ __forceinline__ void red_add_v4(float* addr, float4 v) {
    asm volatile("red.global.v4.f32.add [%0], {%1, %2, %3, %4};"
                 :: "l"(addr), "f"(v.x), "f"(v.y), "f"(v.z), "f"(v.w)
                 : "memory");
}

// Kernel B: leftover slots (~26%) add via vector RED. Independent per thread.
__global__ void red_slots_kernel(const float4* __restrict__ u2,
                                 const float4* __restrict__ u3,
                                 float* __restrict__ out,
                                 int u3_row_base) {
    long long gid = blockIdx.x * (long long)blockDim.x + threadIdx.x;
    int slot = (int)(gid >> 3);
    if (slot >= (int)TOT) return;
    int sub = (int)(gid & 7);

    int2 nd = __ldg(&g_node[slot]);           // coalesced, broadcast per group
    if (nd.x < 0) return;                     // first slot / handled by A
    const float4* feat = (nd.y < u3_row_base) ? u2 : u3;
    float4 v = __ldg(feat + (long long)nd.x * 8 + sub);
    red_add_v4(out + (long long)nd.y * FEAT_D + sub * 4, v);
}

extern "C" void kernel_launch(void* const* d_in, const int* in_sizes, int n_in,
                              void* d_out, int out_size) {
    const float* u2 = (const float*)d_in[0];
    const float* u3 = (const float*)d_in[1];
    const int N3 = in_sizes[2];
    const int N4 = in_sizes[6];

    EdgePtrs ep;
    ep.s[0] = (const int*)d_in[2];  ep.d[0] = (const int*)d_in[3];
    ep.s[1] = (const int*)d_in[4];  ep.d[1] = (const int*)d_in[5];
    ep.s[2] = (const int*)d_in[6];  ep.d[2] = (const int*)d_in[7];
    ep.s[3] = (const int*)d_in[8];  ep.d[3] = (const int*)d_in[9];
    ep.s[4] = (const int*)d_in[10]; ep.d[4] = (const int*)d_in[11];
    ep.s[5] = (const int*)d_in[12]; ep.d[5] = (const int*)d_in[13];
    ep.s[6] = (const int*)d_in[14]; ep.d[6] = (const int*)d_in[15];
    int b = 0;
    ep.ebase[0] = b; b += N3;
    ep.ebase[1] = b; b += N3;
    ep.ebase[2] = b; b += N4;
    ep.ebase[3] = b; b += N4;
    ep.ebase[4] = b; b += N4;
    ep.ebase[5] = b; b += N4;   // first u3-fed relation
    ep.ebase[6] = b; b += N4;
    ep.ebase[7] = b;            // == TOT
    const int u3_row_base = ep.ebase[5];

    float* out = (float*)d_out;
    const int TOTI = (int)TOT;

    // init cnt + s0
    init_kernel<<<(int)((2 * (TOT / 4) + 255) / 256), 256>>>();
    // fused count over all relations
    count_kernel<<<(TOTI + 255) / 256, 256>>>(ep);
    // scan
    scan_block_sum_kernel<<<NB, 256>>>();
    scan_bs_kernel<<<1, 1024>>>();
    scan_fill_off_kernel<<<NB, 256>>>();
    // fused fill
    fill_kernel<<<(TOTI + 255) / 256, 256>>>(ep);

    // A: one store per row (also zeros empty rows)
    {
        long long threads = TOT * 8;
        store_rows_kernel<<<(int)((threads + 255) / 256), 256>>>(
            (const float4*)u2, (const float4*)u3, (float4*)out, u3_row_base);
    }
    // B: leftover slots via vector RED
    {
        long long threads = TOT * 8;
        red_slots_kernel<<<(int)((threads + 255) / 256), 256>>>(
            (const float4*)u2, (const float4*)u3, out, u3_row_base);
    }
}

// round 6
// speedup vs baseline: 1.7881x; 1.7881x over previous
#include <cuda_runtime.h>

// ---------------------------------------------------------------------------
// CarryII R6: R2 structure (edge-parallel red.global.v4.f32.add) + two tweaks:
//  1) zero each output block immediately before its scatter, so the freshly
//     zeroed (dirty-in-L2) tail of the block absorbs atomic RFO reads.
//  2) 2 edges per thread in the scatter for 2x memory-level parallelism.
// Index loads are __ldcs (read-once, don't pollute L2 vs u2 reuse).
// ---------------------------------------------------------------------------

static constexpr int FEAT_D = 32;

__global__ void zero_f4_kernel(float4* __restrict__ out, long long n4) {
    long long i = blockIdx.x * (long long)blockDim.x + threadIdx.x;
    if (i < n4) out[i] = make_float4(0.f, 0.f, 0.f, 0.f);
}

__device__ __forceinline__ void red_add_v4(float* addr, float4 v) {
    asm volatile("red.global.v4.f32.add [%0], {%1, %2, %3, %4};"
                 :: "l"(addr), "f"(v.x), "f"(v.y), "f"(v.z), "f"(v.w)
                 : "memory");
}

// 8 lanes per edge, 2 edges per thread (e and e + nh) for MLP.
__global__ void scatter_add_v4x2_kernel(const float4* __restrict__ feat,
                                        const int* __restrict__ s_idx,
                                        const int* __restrict__ d_idx,
                                        float* __restrict__ out,
                                        int n_edges, int nh) {
    long long gid = blockIdx.x * (long long)blockDim.x + threadIdx.x;
    int pair = (int)(gid >> 3);
    if (pair >= nh) return;
    int sub = (int)(gid & 7);

    int e0 = pair;
    int e1 = pair + nh;
    bool has1 = (e1 < n_edges);

    int s0 = __ldcs(s_idx + e0);
    int d0 = __ldcs(d_idx + e0);
    int s1 = has1 ? __ldcs(s_idx + e1) : 0;
    int d1 = has1 ? __ldcs(d_idx + e1) : 0;

    // two independent 16B gathers (each 8-lane group covers one 128B line)
    float4 v0 = __ldg(feat + (long long)s0 * 8 + sub);
    float4 v1 = has1 ? __ldg(feat + (long long)s1 * 8 + sub)
                     : make_float4(0.f, 0.f, 0.f, 0.f);

    red_add_v4(out + (long long)d0 * FEAT_D + sub * 4, v0);
    if (has1) red_add_v4(out + (long long)d1 * FEAT_D + sub * 4, v1);
}

static inline void launch_block(const float* feat, const int* s, const int* d,
                                float* out_blk, int n_edges, int n_rows) {
    // zero this relation's output block right before scattering into it:
    // the dirty-in-L2 tail absorbs atomic RFO reads.
    long long n4 = (long long)n_rows * 8;                 // float4 per block
    zero_f4_kernel<<<(int)((n4 + 255) / 256), 256>>>((float4*)out_blk, n4);

    int nh = (n_edges + 1) / 2;
    long long threads = (long long)nh * 8;
    int grid = (int)((threads + 255) / 256);
    scatter_add_v4x2_kernel<<<grid, 256>>>((const float4*)feat, s, d,
                                           out_blk, n_edges, nh);
}

extern "C" void kernel_launch(void* const* d_in, const int* in_sizes, int n_in,
                              void* d_out, int out_size) {
    const float* u2 = (const float*)d_in[0];
    const float* u3 = (const float*)d_in[1];

    const int* s_b0a = (const int*)d_in[2];
    const int* d_b0a = (const int*)d_in[3];
    const int* s_b1a = (const int*)d_in[4];
    const int* d_b1a = (const int*)d_in[5];
    const int* s_b0t = (const int*)d_in[6];
    const int* d_b0t = (const int*)d_in[7];
    const int* s_b1t = (const int*)d_in[8];
    const int* d_b1t = (const int*)d_in[9];
    const int* s_b2t = (const int*)d_in[10];
    const int* d_b2t = (const int*)d_in[11];
    const int* s_a0t = (const int*)d_in[12];
    const int* d_a0t = (const int*)d_in[13];
    const int* s_a1t = (const int*)d_in[14];
    const int* d_a1t = (const int*)d_in[15];

    const int N3 = in_sizes[2];
    const int N4 = in_sizes[6];

    float* out = (float*)d_out;
    const long long blk3 = (long long)N3 * FEAT_D;
    const long long blk4 = (long long)N4 * FEAT_D;

    float* o = out;
    launch_block(u2, s_b0a, d_b0a, o, N3, N3); o += blk3;  // u_left
    launch_block(u2, s_b1a, d_b1a, o, N3, N3); o += blk3;  // u_right
    launch_block(u2, s_b0t, d_b0t, o, N4, N4); o += blk4;  // u_bond_left
    launch_block(u2, s_b1t, d_b1t, o, N4, N4); o += blk4;  // u_bond_center
    launch_block(u2, s_b2t, d_b2t, o, N4, N4); o += blk4;  // u_bond_right
    launch_block(u3, s_a0t, d_a0t, o, N4, N4); o += blk4;  // u_angle_left
    launch_block(u3, s_a1t, d_a1t, o, N4, N4);             // u_angle_right
}